// round 15
// baseline (speedup 1.0000x reference)
#include <cuda_runtime.h>
#include <cstdint>

#define N_NODES 50000
#define N_EDGES 800000
#define D 128
#define NCLS 64
#define SCAN_B 1024
#define SCAN_NBLK ((N_NODES + SCAN_B - 1) / SCAN_B)   // 49

// ---------------------------------------------------------------------------
// Device-global scratch
// ---------------------------------------------------------------------------
__device__ __align__(16) float g_y[N_NODES * D];
__device__ __align__(16) float g_h[N_NODES * D];
__device__ int g_row_ptr[N_NODES + 1];
__device__ int g_cursor[N_NODES];
__device__ int g_cnt[N_NODES];
__device__ int g_col[N_EDGES];
__device__ int g_partials[SCAN_NBLK];

// ---------------------------------------------------------------------------
// CSR kernels (unchanged)
// ---------------------------------------------------------------------------
__global__ void __launch_bounds__(256) hist_kernel(
    const int* __restrict__ dst, int* __restrict__ cnt)
{
    int base = (blockIdx.x * blockDim.x + threadIdx.x) * 4;
    if (base + 3 < N_EDGES) {
        int4 d4 = *reinterpret_cast<const int4*>(dst + base);
        atomicAdd(cnt + d4.x, 1);
        atomicAdd(cnt + d4.y, 1);
        atomicAdd(cnt + d4.z, 1);
        atomicAdd(cnt + d4.w, 1);
    } else {
        for (int e = base; e < N_EDGES; e++) atomicAdd(cnt + dst[e], 1);
    }
}

__global__ void __launch_bounds__(SCAN_B) scan_block_kernel(
    const int* __restrict__ cnt, int* __restrict__ row_ptr, int* __restrict__ partials)
{
    __shared__ int wsum[32];
    int i = blockIdx.x * SCAN_B + threadIdx.x;
    int lane = threadIdx.x & 31;
    int wid  = threadIdx.x >> 5;

    int v = (i < N_NODES) ? cnt[i] : 0;
    int x = v;
    #pragma unroll
    for (int off = 1; off < 32; off <<= 1) {
        int t = __shfl_up_sync(0xffffffffu, x, off);
        if (lane >= off) x += t;
    }
    if (lane == 31) wsum[wid] = x;
    __syncthreads();
    if (wid == 0) {
        int w = wsum[lane];
        #pragma unroll
        for (int off = 1; off < 32; off <<= 1) {
            int t = __shfl_up_sync(0xffffffffu, w, off);
            if (lane >= off) w += t;
        }
        wsum[lane] = w;
    }
    __syncthreads();

    int excl = x - v + (wid ? wsum[wid - 1] : 0);
    if (i < N_NODES) row_ptr[i] = excl;
    if (threadIdx.x == SCAN_B - 1) partials[blockIdx.x] = excl + v;
}

__global__ void __launch_bounds__(SCAN_B) scan_add_kernel(
    int* __restrict__ row_ptr, int* __restrict__ cursor, const int* __restrict__ partials)
{
    __shared__ int sp[SCAN_NBLK];
    if (threadIdx.x < SCAN_NBLK) sp[threadIdx.x] = partials[threadIdx.x];
    __syncthreads();
    if (threadIdx.x == 0) {
        int run = 0;
        #pragma unroll
        for (int k = 0; k < SCAN_NBLK; k++) { int t = sp[k]; sp[k] = run; run += t; }
    }
    __syncthreads();

    int i = blockIdx.x * SCAN_B + threadIdx.x;
    if (i < N_NODES) {
        int r = row_ptr[i] + sp[blockIdx.x];
        row_ptr[i] = r;
        cursor[i]  = r;
    }
    if (i == 0) row_ptr[N_NODES] = N_EDGES;
}

__global__ void __launch_bounds__(256) fill_kernel(
    const int* __restrict__ src, const int* __restrict__ dst,
    int* __restrict__ cursor, int* __restrict__ col)
{
    int base = (blockIdx.x * blockDim.x + threadIdx.x) * 4;
    if (base + 3 < N_EDGES) {
        int4 d4 = *reinterpret_cast<const int4*>(dst + base);
        int4 s4 = *reinterpret_cast<const int4*>(src + base);
        int p0 = atomicAdd(cursor + d4.x, 1);
        int p1 = atomicAdd(cursor + d4.y, 1);
        int p2 = atomicAdd(cursor + d4.z, 1);
        int p3 = atomicAdd(cursor + d4.w, 1);
        col[p0] = s4.x; col[p1] = s4.y; col[p2] = s4.z; col[p3] = s4.w;
    } else {
        for (int e = base; e < N_EDGES; e++) {
            int pos = atomicAdd(cursor + dst[e], 1);
            col[pos] = src[e];
        }
    }
}

// ---------------------------------------------------------------------------
// K-PAIRED f32x2 GEMM: acc2 += (a_k0,a_k1)*(w_k0,w_k1); result = lo+hi at end.
//  - zero operand-duplication MOVs (31% of R13's issue slots)
//  - sX row-major (a = broadcast LDS.128 over 4 k's, as R13)
//  - sW2 k-pair-major: row k2 holds (W[n][2k2], W[n][2k2+1]) at float 2n;
//    thread's column groups of 2 at 4*tx -> every 8-thread phase covers
//    banks 0..31 exactly once (conflict-free LDS.128)
//  - 256 threads, 32 outputs/thread -> 64 acc regs; lb(256,2) caps 128 regs
//    (live ~110, no spill), 2 blocks/SM = 16 warps/SM
// y[n,j] = sum_k A[n,k] * W[j,k]
// ---------------------------------------------------------------------------
template <int NOUT>
__global__ void __launch_bounds__(256, 2) gemm_kernel(
    const float* __restrict__ A, const float* __restrict__ W, float* __restrict__ y)
{
    constexpr int BM    = 64;
    constexpr int KC    = 64;
    constexpr int TX    = NOUT / 8;        // 16 (128) or 8 (64): 8 cols/thread
    constexpr int TY    = 256 / TX;        // 16 or 32
    constexpr int RPT   = BM / TY;         // 4 or 2 rows/thread
    constexpr int SXS   = KC + 4;          // 68 (row 272B, 16B-aligned)
    constexpr int SW2S  = 2 * NOUT + 8;    // 264 or 136 floats (16B-aligned rows)
    constexpr int GSPAN = NOUT / 2;        // floats per col-group per k2 row
    constexpr int COLQ  = NOUT / 4;        // column span of one group

    extern __shared__ float smem[];
    float* sX  = smem;                     // [BM][SXS] row-major
    float* sW2 = smem + BM * SXS;          // [KC/2][SW2S] k-pair-major

    const int tid  = threadIdx.x;
    const int row0 = blockIdx.x * BM;
    const int tx   = tid % TX;
    const int ty   = tid / TX;
    const int rbase = ty * RPT;

    // acc[r][2g+p] accumulates (even-k, odd-k) partials for col g*COLQ + 2*tx + p
    unsigned long long acc[RPT][8];
    #pragma unroll
    for (int r = 0; r < RPT; r++)
        #pragma unroll
        for (int c = 0; c < 8; c++) acc[r][c] = 0ULL;

    #pragma unroll
    for (int kc = 0; kc < D; kc += KC) {
        // X chunk [BM][KC], coalesced float4 loads, row-major store
        #pragma unroll
        for (int i = tid; i < BM * (KC / 4); i += 256) {
            int r  = i >> 4;               // KC/4 == 16
            int c4 = i & 15;
            int gr = row0 + r;
            float4 v = make_float4(0.f, 0.f, 0.f, 0.f);
            if (gr < N_NODES)
                v = *reinterpret_cast<const float4*>(A + (size_t)gr * D + kc + c4 * 4);
            reinterpret_cast<float4*>(sX + r * SXS)[c4] = v;
        }
        // W chunk -> sW2 k-pair-major: row k2=2*k4(+1), float2 at 2n
        #pragma unroll
        for (int i = tid; i < NOUT * (KC / 4); i += 256) {
            int n  = i >> 4;
            int k4 = i & 15;
            float4 v = *reinterpret_cast<const float4*>(W + (size_t)n * D + kc + k4 * 4);
            *reinterpret_cast<float2*>(sW2 + (k4 * 2 + 0) * SW2S + 2 * n) =
                make_float2(v.x, v.y);
            *reinterpret_cast<float2*>(sW2 + (k4 * 2 + 1) * SW2S + 2 * n) =
                make_float2(v.z, v.w);
        }
        __syncthreads();

        #pragma unroll 2
        for (int k4 = 0; k4 < KC; k4 += 4) {
            // a: per row one LDS.128 = 2 k-pairs (broadcast across tx)
            ulonglong2 av[RPT];
            #pragma unroll
            for (int r = 0; r < RPT; r++)
                av[r] = *reinterpret_cast<const ulonglong2*>(sX + (rbase + r) * SXS + k4);

            #pragma unroll
            for (int kp = 0; kp < 2; kp++) {
                const float* swk = sW2 + ((k4 >> 1) + kp) * SW2S + 4 * tx;
                ulonglong2 bg0 = *reinterpret_cast<const ulonglong2*>(swk + 0 * GSPAN);
                ulonglong2 bg1 = *reinterpret_cast<const ulonglong2*>(swk + 1 * GSPAN);
                ulonglong2 bg2 = *reinterpret_cast<const ulonglong2*>(swk + 2 * GSPAN);
                ulonglong2 bg3 = *reinterpret_cast<const ulonglong2*>(swk + 3 * GSPAN);
                #pragma unroll
                for (int r = 0; r < RPT; r++) {
                    unsigned long long a2 = kp ? av[r].y : av[r].x;
                    asm("fma.rn.f32x2 %0, %1, %2, %0;" : "+l"(acc[r][0]) : "l"(a2), "l"(bg0.x));
                    asm("fma.rn.f32x2 %0, %1, %2, %0;" : "+l"(acc[r][1]) : "l"(a2), "l"(bg0.y));
                    asm("fma.rn.f32x2 %0, %1, %2, %0;" : "+l"(acc[r][2]) : "l"(a2), "l"(bg1.x));
                    asm("fma.rn.f32x2 %0, %1, %2, %0;" : "+l"(acc[r][3]) : "l"(a2), "l"(bg1.y));
                    asm("fma.rn.f32x2 %0, %1, %2, %0;" : "+l"(acc[r][4]) : "l"(a2), "l"(bg2.x));
                    asm("fma.rn.f32x2 %0, %1, %2, %0;" : "+l"(acc[r][5]) : "l"(a2), "l"(bg2.y));
                    asm("fma.rn.f32x2 %0, %1, %2, %0;" : "+l"(acc[r][6]) : "l"(a2), "l"(bg3.x));
                    asm("fma.rn.f32x2 %0, %1, %2, %0;" : "+l"(acc[r][7]) : "l"(a2), "l"(bg3.y));
                }
            }
        }
        __syncthreads();
    }

    // Epilogue: result = lo + hi (even-k + odd-k partials)
    #pragma unroll
    for (int r = 0; r < RPT; r++) {
        int row = row0 + rbase + r;
        if (row >= N_NODES) continue;
        #pragma unroll
        for (int g = 0; g < 4; g++) {
            float lo0, hi0, lo1, hi1;
            asm("mov.b64 {%0, %1}, %2;" : "=f"(lo0), "=f"(hi0) : "l"(acc[r][2*g]));
            asm("mov.b64 {%0, %1}, %2;" : "=f"(lo1), "=f"(hi1) : "l"(acc[r][2*g+1]));
            *reinterpret_cast<float2*>(y + (size_t)row * NOUT + g * COLQ + 2 * tx) =
                make_float2(lo0 + hi0, lo1 + hi1);
        }
    }
}

// ---------------------------------------------------------------------------
// CSR aggregation + bias + relu (unchanged: unroll-4, warp per node)
// ---------------------------------------------------------------------------
__global__ void __launch_bounds__(256) aggregate128_kernel(
    const float* __restrict__ y, const int* __restrict__ row_ptr,
    const int* __restrict__ col, const float* __restrict__ bias,
    float* __restrict__ out)
{
    int node = (blockIdx.x * blockDim.x + threadIdx.x) >> 5;
    int lane = threadIdx.x & 31;
    if (node >= N_NODES) return;

    int beg = __ldg(row_ptr + node);
    int end = __ldg(row_ptr + node + 1);

    const float4* base = reinterpret_cast<const float4*>(y);
    float4 acc = base[(size_t)node * 32 + lane];
    float4 acc2 = make_float4(0.f, 0.f, 0.f, 0.f);

    int j = beg;
    for (; j + 3 < end; j += 4) {
        int c0 = __ldg(col + j);
        int c1 = __ldg(col + j + 1);
        int c2 = __ldg(col + j + 2);
        int c3 = __ldg(col + j + 3);
        float4 v0 = base[(size_t)c0 * 32 + lane];
        float4 v1 = base[(size_t)c1 * 32 + lane];
        float4 v2 = base[(size_t)c2 * 32 + lane];
        float4 v3 = base[(size_t)c3 * 32 + lane];
        acc.x  += v0.x; acc.y  += v0.y; acc.z  += v0.z; acc.w  += v0.w;
        acc2.x += v1.x; acc2.y += v1.y; acc2.z += v1.z; acc2.w += v1.w;
        acc.x  += v2.x; acc.y  += v2.y; acc.z  += v2.z; acc.w  += v2.w;
        acc2.x += v3.x; acc2.y += v3.y; acc2.z += v3.z; acc2.w += v3.w;
    }
    for (; j < end; j++) {
        int c0 = __ldg(col + j);
        float4 v0 = base[(size_t)c0 * 32 + lane];
        acc.x += v0.x; acc.y += v0.y; acc.z += v0.z; acc.w += v0.w;
    }
    acc.x += acc2.x; acc.y += acc2.y; acc.z += acc2.z; acc.w += acc2.w;

    float4 b = reinterpret_cast<const float4*>(bias)[lane];
    float4 o;
    o.x = fmaxf(acc.x + b.x, 0.f);
    o.y = fmaxf(acc.y + b.y, 0.f);
    o.z = fmaxf(acc.z + b.z, 0.f);
    o.w = fmaxf(acc.w + b.w, 0.f);
    reinterpret_cast<float4*>(out)[(size_t)node * 32 + lane] = o;
}

__global__ void __launch_bounds__(256) aggregate64_kernel(
    const float* __restrict__ y, const int* __restrict__ row_ptr,
    const int* __restrict__ col, const float* __restrict__ bias,
    float* __restrict__ out)
{
    int node = (blockIdx.x * blockDim.x + threadIdx.x) >> 5;
    int lane = threadIdx.x & 31;
    if (node >= N_NODES) return;

    int beg = __ldg(row_ptr + node);
    int end = __ldg(row_ptr + node + 1);

    const float2* base = reinterpret_cast<const float2*>(y);
    float2 acc = base[(size_t)node * 32 + lane];
    float2 acc2 = make_float2(0.f, 0.f);

    int j = beg;
    for (; j + 3 < end; j += 4) {
        int c0 = __ldg(col + j);
        int c1 = __ldg(col + j + 1);
        int c2 = __ldg(col + j + 2);
        int c3 = __ldg(col + j + 3);
        float2 v0 = base[(size_t)c0 * 32 + lane];
        float2 v1 = base[(size_t)c1 * 32 + lane];
        float2 v2 = base[(size_t)c2 * 32 + lane];
        float2 v3 = base[(size_t)c3 * 32 + lane];
        acc.x  += v0.x; acc.y  += v0.y;
        acc2.x += v1.x; acc2.y += v1.y;
        acc.x  += v2.x; acc.y  += v2.y;
        acc2.x += v3.x; acc2.y += v3.y;
    }
    for (; j < end; j++) {
        int c0 = __ldg(col + j);
        float2 v0 = base[(size_t)c0 * 32 + lane];
        acc.x += v0.x; acc.y += v0.y;
    }
    acc.x += acc2.x; acc.y += acc2.y;

    float2 b = reinterpret_cast<const float2*>(bias)[lane];
    float2 o;
    o.x = fmaxf(acc.x + b.x, 0.f);
    o.y = fmaxf(acc.y + b.y, 0.f);
    reinterpret_cast<float2*>(out)[(size_t)node * 32 + lane] = o;
}

// ---------------------------------------------------------------------------
// Launch: single stream, gemm1 in slot 4 (ncu lands there)
// ---------------------------------------------------------------------------
extern "C" void kernel_launch(void* const* d_in, const int* in_sizes, int n_in,
                              void* d_out, int out_size)
{
    const float* in_feat = (const float*)d_in[0];
    const float* W1 = (const float*)d_in[1];
    const float* b1 = (const float*)d_in[2];
    const float* W2 = (const float*)d_in[3];
    const float* b2 = (const float*)d_in[4];
    const float* W3 = (const float*)d_in[5];
    const float* b3 = (const float*)d_in[6];
    const int*   src = (const int*)d_in[7];
    const int*   dst = (const int*)d_in[8];
    float* out = (float*)d_out;

    float *y, *h;
    int *row_ptr, *cursor, *cnt, *col, *partials;
    cudaGetSymbolAddress((void**)&y, g_y);
    cudaGetSymbolAddress((void**)&h, g_h);
    cudaGetSymbolAddress((void**)&row_ptr, g_row_ptr);
    cudaGetSymbolAddress((void**)&cursor, g_cursor);
    cudaGetSymbolAddress((void**)&cnt, g_cnt);
    cudaGetSymbolAddress((void**)&col, g_col);
    cudaGetSymbolAddress((void**)&partials, g_partials);

    const int smem128 = (64 * (64 + 4) + 32 * (2 * 128 + 8)) * (int)sizeof(float); // ~50KB
    const int smem64  = (64 * (64 + 4) + 32 * (2 * 64 + 8))  * (int)sizeof(float); // ~34KB
    cudaFuncSetAttribute(gemm_kernel<128>,
                         cudaFuncAttributeMaxDynamicSharedMemorySize, smem128);
    cudaFuncSetAttribute(gemm_kernel<64>,
                         cudaFuncAttributeMaxDynamicSharedMemorySize, smem64);

    const int edge4_blocks = (N_EDGES / 4 + 255) / 256;
    const int gemm_blocks  = (N_NODES + 63) / 64;
    const int agg_blocks   = (N_NODES * 32 + 255) / 256;

    // ---- CSR + layer-1 GEMM ----
    cudaMemsetAsync(cnt, 0, N_NODES * sizeof(int), 0);
    hist_kernel<<<edge4_blocks, 256>>>(dst, cnt);                       // 1
    scan_block_kernel<<<SCAN_NBLK, SCAN_B>>>(cnt, row_ptr, partials);   // 2
    scan_add_kernel<<<SCAN_NBLK, SCAN_B>>>(row_ptr, cursor, partials);  // 3
    gemm_kernel<128><<<gemm_blocks, 256, smem128>>>(in_feat, W1, y);    // 4 <- ncu
    fill_kernel<<<edge4_blocks, 256>>>(src, dst, cursor, col);          // 5

    // ---- Layer 1 boundary: h = relu(y + Ay + b1) ----
    aggregate128_kernel<<<agg_blocks, 256>>>(y, row_ptr, col, b1, h);   // 6

    // ---- Layer 2: y = h @ W2 ; h = relu(y + Ay + b2) ----
    gemm_kernel<128><<<gemm_blocks, 256, smem128>>>(h, W2, y);          // 7
    aggregate128_kernel<<<agg_blocks, 256>>>(y, row_ptr, col, b2, h);   // 8

    // ---- Layer 3: y = h @ W3 (64) ; out = relu(y + Ay + b3) ----
    gemm_kernel<64><<<gemm_blocks, 256, smem64>>>(h, W3, y);            // 9
    aggregate64_kernel<<<agg_blocks, 256>>>(y, row_ptr, col, b3, out);  // 10
}

// round 16
// speedup vs baseline: 1.1755x; 1.1755x over previous
#include <cuda_runtime.h>
#include <cstdint>

#define N_NODES 50000
#define N_EDGES 800000
#define D 128
#define NCLS 64
#define SCAN_B 1024
#define SCAN_NBLK ((N_NODES + SCAN_B - 1) / SCAN_B)   // 49

// ---------------------------------------------------------------------------
// Device-global scratch
// ---------------------------------------------------------------------------
__device__ __align__(16) float g_y[N_NODES * D];
__device__ __align__(16) float g_h[N_NODES * D];
__device__ int g_row_ptr[N_NODES + 1];
__device__ int g_cursor[N_NODES];
__device__ int g_cnt[N_NODES];
__device__ int g_col[N_EDGES];
__device__ int g_partials[SCAN_NBLK];

// Streams + events created once at static-init (outside capture & checkpoints)
struct OverlapCtx {
    cudaStream_t s1;
    cudaEvent_t evFork, evCSR;
    OverlapCtx() {
        cudaStreamCreateWithFlags(&s1, cudaStreamNonBlocking);
        cudaEventCreateWithFlags(&evFork, cudaEventDisableTiming);
        cudaEventCreateWithFlags(&evCSR,  cudaEventDisableTiming);
    }
};
static OverlapCtx g_ctx;

// ---------------------------------------------------------------------------
// CSR kernels — hist/fill now 8 edges/thread (R8 profile: issue 1.5%,
// pure ATOMG-latency-bound; 8 independent atomics in flight halves time)
// ---------------------------------------------------------------------------
__global__ void __launch_bounds__(256) hist_kernel(
    const int* __restrict__ dst, int* __restrict__ cnt)
{
    int base = (blockIdx.x * blockDim.x + threadIdx.x) * 8;
    if (base + 7 < N_EDGES) {
        int4 a = *reinterpret_cast<const int4*>(dst + base);
        int4 b = *reinterpret_cast<const int4*>(dst + base + 4);
        atomicAdd(cnt + a.x, 1); atomicAdd(cnt + a.y, 1);
        atomicAdd(cnt + a.z, 1); atomicAdd(cnt + a.w, 1);
        atomicAdd(cnt + b.x, 1); atomicAdd(cnt + b.y, 1);
        atomicAdd(cnt + b.z, 1); atomicAdd(cnt + b.w, 1);
    } else {
        for (int e = base; e < N_EDGES; e++) atomicAdd(cnt + dst[e], 1);
    }
}

__global__ void __launch_bounds__(SCAN_B) scan_block_kernel(
    const int* __restrict__ cnt, int* __restrict__ row_ptr, int* __restrict__ partials)
{
    __shared__ int wsum[32];
    int i = blockIdx.x * SCAN_B + threadIdx.x;
    int lane = threadIdx.x & 31;
    int wid  = threadIdx.x >> 5;

    int v = (i < N_NODES) ? cnt[i] : 0;
    int x = v;
    #pragma unroll
    for (int off = 1; off < 32; off <<= 1) {
        int t = __shfl_up_sync(0xffffffffu, x, off);
        if (lane >= off) x += t;
    }
    if (lane == 31) wsum[wid] = x;
    __syncthreads();
    if (wid == 0) {
        int w = wsum[lane];
        #pragma unroll
        for (int off = 1; off < 32; off <<= 1) {
            int t = __shfl_up_sync(0xffffffffu, w, off);
            if (lane >= off) w += t;
        }
        wsum[lane] = w;
    }
    __syncthreads();

    int excl = x - v + (wid ? wsum[wid - 1] : 0);
    if (i < N_NODES) row_ptr[i] = excl;
    if (threadIdx.x == SCAN_B - 1) partials[blockIdx.x] = excl + v;
}

__global__ void __launch_bounds__(SCAN_B) scan_add_kernel(
    int* __restrict__ row_ptr, int* __restrict__ cursor, const int* __restrict__ partials)
{
    __shared__ int sp[SCAN_NBLK];
    if (threadIdx.x < SCAN_NBLK) sp[threadIdx.x] = partials[threadIdx.x];
    __syncthreads();
    if (threadIdx.x == 0) {
        int run = 0;
        #pragma unroll
        for (int k = 0; k < SCAN_NBLK; k++) { int t = sp[k]; sp[k] = run; run += t; }
    }
    __syncthreads();

    int i = blockIdx.x * SCAN_B + threadIdx.x;
    if (i < N_NODES) {
        int r = row_ptr[i] + sp[blockIdx.x];
        row_ptr[i] = r;
        cursor[i]  = r;
    }
    if (i == 0) row_ptr[N_NODES] = N_EDGES;
}

__global__ void __launch_bounds__(256) fill_kernel(
    const int* __restrict__ src, const int* __restrict__ dst,
    int* __restrict__ cursor, int* __restrict__ col)
{
    int base = (blockIdx.x * blockDim.x + threadIdx.x) * 8;
    if (base + 7 < N_EDGES) {
        int4 da = *reinterpret_cast<const int4*>(dst + base);
        int4 db = *reinterpret_cast<const int4*>(dst + base + 4);
        int4 sa = *reinterpret_cast<const int4*>(src + base);
        int4 sb = *reinterpret_cast<const int4*>(src + base + 4);
        int p0 = atomicAdd(cursor + da.x, 1);
        int p1 = atomicAdd(cursor + da.y, 1);
        int p2 = atomicAdd(cursor + da.z, 1);
        int p3 = atomicAdd(cursor + da.w, 1);
        int p4 = atomicAdd(cursor + db.x, 1);
        int p5 = atomicAdd(cursor + db.y, 1);
        int p6 = atomicAdd(cursor + db.z, 1);
        int p7 = atomicAdd(cursor + db.w, 1);
        col[p0] = sa.x; col[p1] = sa.y; col[p2] = sa.z; col[p3] = sa.w;
        col[p4] = sb.x; col[p5] = sb.y; col[p6] = sb.z; col[p7] = sb.w;
    } else {
        for (int e = base; e < N_EDGES; e++) {
            int pos = atomicAdd(cursor + dst[e], 1);
            col[pos] = src[e];
        }
    }
}

// ---------------------------------------------------------------------------
// f32x2 GEMM — R14 verified best (frozen): BM=64, KC=64, 128 thr, 8r x 8c,
// vectorized a-loads, split conflict-free b-groups, lb(128,4).
// ---------------------------------------------------------------------------
template <int NOUT>
__global__ void __launch_bounds__(128, 4) gemm_kernel(
    const float* __restrict__ A, const float* __restrict__ W, float* __restrict__ y)
{
    constexpr int BM   = 64;
    constexpr int KC   = 64;
    constexpr int TX   = NOUT / 8;
    constexpr int TY   = 128 / TX;
    constexpr int RPT  = BM / TY;
    constexpr int SXS  = KC + 4;
    constexpr int SWS  = NOUT + 4;
    constexpr int HALF = NOUT / 2;

    extern __shared__ float smem[];
    float* sX = smem;
    float* sW = smem + BM * SXS;

    const int tid  = threadIdx.x;
    const int row0 = blockIdx.x * BM;

    const int tx = tid % TX;
    const int ty = tid / TX;
    const int cb0 = tx * 4;
    const int cb1 = HALF + tx * 4;
    const int rbase = ty * RPT;

    unsigned long long acc[RPT][4];
    #pragma unroll
    for (int r = 0; r < RPT; r++)
        #pragma unroll
        for (int c = 0; c < 4; c++) acc[r][c] = 0ULL;

    #pragma unroll
    for (int kc = 0; kc < D; kc += KC) {
        #pragma unroll
        for (int i = tid; i < BM * (KC / 4); i += 128) {
            int r  = i >> 4;
            int c4 = i & 15;
            int gr = row0 + r;
            float4 v = make_float4(0.f, 0.f, 0.f, 0.f);
            if (gr < N_NODES)
                v = *reinterpret_cast<const float4*>(A + (size_t)gr * D + kc + c4 * 4);
            reinterpret_cast<float4*>(sX + r * SXS)[c4] = v;
        }
        #pragma unroll
        for (int i = tid; i < NOUT * (KC / 4); i += 128) {
            int n  = i >> 4;
            int k4 = i & 15;
            float4 v = *reinterpret_cast<const float4*>(W + (size_t)n * D + kc + k4 * 4);
            sW[(k4 * 4 + 0) * SWS + n] = v.x;
            sW[(k4 * 4 + 1) * SWS + n] = v.y;
            sW[(k4 * 4 + 2) * SWS + n] = v.z;
            sW[(k4 * 4 + 3) * SWS + n] = v.w;
        }
        __syncthreads();

        #pragma unroll 2
        for (int k4 = 0; k4 < KC; k4 += 4) {
            float4 av[RPT];
            #pragma unroll
            for (int r = 0; r < RPT; r++)
                av[r] = *reinterpret_cast<const float4*>(sX + (rbase + r) * SXS + k4);

            #pragma unroll
            for (int kk = 0; kk < 4; kk++) {
                const float* swk = sW + (k4 + kk) * SWS;
                ulonglong2 b0 = *reinterpret_cast<const ulonglong2*>(swk + cb0);
                ulonglong2 b1 = *reinterpret_cast<const ulonglong2*>(swk + cb1);
                #pragma unroll
                for (int r = 0; r < RPT; r++) {
                    float a = (kk == 0) ? av[r].x : (kk == 1) ? av[r].y
                            : (kk == 2) ? av[r].z : av[r].w;
                    unsigned long long a2;
                    asm("mov.b64 %0, {%1, %1};" : "=l"(a2) : "f"(a));
                    asm("fma.rn.f32x2 %0, %1, %2, %0;" : "+l"(acc[r][0]) : "l"(a2), "l"(b0.x));
                    asm("fma.rn.f32x2 %0, %1, %2, %0;" : "+l"(acc[r][1]) : "l"(a2), "l"(b0.y));
                    asm("fma.rn.f32x2 %0, %1, %2, %0;" : "+l"(acc[r][2]) : "l"(a2), "l"(b1.x));
                    asm("fma.rn.f32x2 %0, %1, %2, %0;" : "+l"(acc[r][3]) : "l"(a2), "l"(b1.y));
                }
            }
        }
        __syncthreads();
    }

    #pragma unroll
    for (int r = 0; r < RPT; r++) {
        int row = row0 + rbase + r;
        if (row >= N_NODES) continue;
        float o[8];
        #pragma unroll
        for (int c = 0; c < 4; c++)
            asm("mov.b64 {%0, %1}, %2;" : "=f"(o[2*c]), "=f"(o[2*c+1]) : "l"(acc[r][c]));
        *reinterpret_cast<float4*>(y + (size_t)row * NOUT + cb0) =
            make_float4(o[0], o[1], o[2], o[3]);
        *reinterpret_cast<float4*>(y + (size_t)row * NOUT + cb1) =
            make_float4(o[4], o[5], o[6], o[7]);
    }
}

// ---------------------------------------------------------------------------
// CSR aggregation + bias + relu (frozen: unroll-4, warp per node)
// ---------------------------------------------------------------------------
__global__ void __launch_bounds__(256) aggregate128_kernel(
    const float* __restrict__ y, const int* __restrict__ row_ptr,
    const int* __restrict__ col, const float* __restrict__ bias,
    float* __restrict__ out)
{
    int node = (blockIdx.x * blockDim.x + threadIdx.x) >> 5;
    int lane = threadIdx.x & 31;
    if (node >= N_NODES) return;

    int beg = __ldg(row_ptr + node);
    int end = __ldg(row_ptr + node + 1);

    const float4* base = reinterpret_cast<const float4*>(y);
    float4 acc = base[(size_t)node * 32 + lane];
    float4 acc2 = make_float4(0.f, 0.f, 0.f, 0.f);

    int j = beg;
    for (; j + 3 < end; j += 4) {
        int c0 = __ldg(col + j);
        int c1 = __ldg(col + j + 1);
        int c2 = __ldg(col + j + 2);
        int c3 = __ldg(col + j + 3);
        float4 v0 = base[(size_t)c0 * 32 + lane];
        float4 v1 = base[(size_t)c1 * 32 + lane];
        float4 v2 = base[(size_t)c2 * 32 + lane];
        float4 v3 = base[(size_t)c3 * 32 + lane];
        acc.x  += v0.x; acc.y  += v0.y; acc.z  += v0.z; acc.w  += v0.w;
        acc2.x += v1.x; acc2.y += v1.y; acc2.z += v1.z; acc2.w += v1.w;
        acc.x  += v2.x; acc.y  += v2.y; acc.z  += v2.z; acc.w  += v2.w;
        acc2.x += v3.x; acc2.y += v3.y; acc2.z += v3.z; acc2.w += v3.w;
    }
    for (; j < end; j++) {
        int c0 = __ldg(col + j);
        float4 v0 = base[(size_t)c0 * 32 + lane];
        acc.x += v0.x; acc.y += v0.y; acc.z += v0.z; acc.w += v0.w;
    }
    acc.x += acc2.x; acc.y += acc2.y; acc.z += acc2.z; acc.w += acc2.w;

    float4 b = reinterpret_cast<const float4*>(bias)[lane];
    float4 o;
    o.x = fmaxf(acc.x + b.x, 0.f);
    o.y = fmaxf(acc.y + b.y, 0.f);
    o.z = fmaxf(acc.z + b.z, 0.f);
    o.w = fmaxf(acc.w + b.w, 0.f);
    reinterpret_cast<float4*>(out)[(size_t)node * 32 + lane] = o;
}

__global__ void __launch_bounds__(256) aggregate64_kernel(
    const float* __restrict__ y, const int* __restrict__ row_ptr,
    const int* __restrict__ col, const float* __restrict__ bias,
    float* __restrict__ out)
{
    int node = (blockIdx.x * blockDim.x + threadIdx.x) >> 5;
    int lane = threadIdx.x & 31;
    if (node >= N_NODES) return;

    int beg = __ldg(row_ptr + node);
    int end = __ldg(row_ptr + node + 1);

    const float2* base = reinterpret_cast<const float2*>(y);
    float2 acc = base[(size_t)node * 32 + lane];
    float2 acc2 = make_float2(0.f, 0.f);

    int j = beg;
    for (; j + 3 < end; j += 4) {
        int c0 = __ldg(col + j);
        int c1 = __ldg(col + j + 1);
        int c2 = __ldg(col + j + 2);
        int c3 = __ldg(col + j + 3);
        float2 v0 = base[(size_t)c0 * 32 + lane];
        float2 v1 = base[(size_t)c1 * 32 + lane];
        float2 v2 = base[(size_t)c2 * 32 + lane];
        float2 v3 = base[(size_t)c3 * 32 + lane];
        acc.x  += v0.x; acc.y  += v0.y;
        acc2.x += v1.x; acc2.y += v1.y;
        acc.x  += v2.x; acc.y  += v2.y;
        acc2.x += v3.x; acc2.y += v3.y;
    }
    for (; j < end; j++) {
        int c0 = __ldg(col + j);
        float2 v0 = base[(size_t)c0 * 32 + lane];
        acc.x += v0.x; acc.y += v0.y;
    }
    acc.x += acc2.x; acc.y += acc2.y;

    float2 b = reinterpret_cast<const float2*>(bias)[lane];
    float2 o;
    o.x = fmaxf(acc.x + b.x, 0.f);
    o.y = fmaxf(acc.y + b.y, 0.f);
    reinterpret_cast<float2*>(out)[(size_t)node * 32 + lane] = o;
}

// ---------------------------------------------------------------------------
// Launch: CSR (s1) ∥ gemm1 (s0), then serial. R6-style fork (measured −10.6us
// vs serial with identical kernels); kernels themselves are R14's best.
// ---------------------------------------------------------------------------
extern "C" void kernel_launch(void* const* d_in, const int* in_sizes, int n_in,
                              void* d_out, int out_size)
{
    const float* in_feat = (const float*)d_in[0];
    const float* W1 = (const float*)d_in[1];
    const float* b1 = (const float*)d_in[2];
    const float* W2 = (const float*)d_in[3];
    const float* b2 = (const float*)d_in[4];
    const float* W3 = (const float*)d_in[5];
    const float* b3 = (const float*)d_in[6];
    const int*   src = (const int*)d_in[7];
    const int*   dst = (const int*)d_in[8];
    float* out = (float*)d_out;

    float *y, *h;
    int *row_ptr, *cursor, *cnt, *col, *partials;
    cudaGetSymbolAddress((void**)&y, g_y);
    cudaGetSymbolAddress((void**)&h, g_h);
    cudaGetSymbolAddress((void**)&row_ptr, g_row_ptr);
    cudaGetSymbolAddress((void**)&cursor, g_cursor);
    cudaGetSymbolAddress((void**)&cnt, g_cnt);
    cudaGetSymbolAddress((void**)&col, g_col);
    cudaGetSymbolAddress((void**)&partials, g_partials);

    const int smem128 = (64 * (64 + 4) + 64 * (128 + 4)) * (int)sizeof(float);  // ~51KB
    const int smem64  = (64 * (64 + 4) + 64 * (64 + 4))  * (int)sizeof(float);  // ~35KB
    cudaFuncSetAttribute(gemm_kernel<128>,
                         cudaFuncAttributeMaxDynamicSharedMemorySize, smem128);
    cudaFuncSetAttribute(gemm_kernel<64>,
                         cudaFuncAttributeMaxDynamicSharedMemorySize, smem64);

    cudaStream_t s0 = 0;
    cudaStream_t s1 = g_ctx.s1;

    const int edge8_blocks = (N_EDGES / 8 + 255) / 256;
    const int gemm_blocks  = (N_NODES + 63) / 64;
    const int agg_blocks   = (N_NODES * 32 + 255) / 256;

    // Fork: CSR on s1 concurrent with layer-1 GEMM on s0
    cudaEventRecord(g_ctx.evFork, s0);
    cudaStreamWaitEvent(s1, g_ctx.evFork, 0);

    gemm_kernel<128><<<gemm_blocks, 128, smem128, s0>>>(in_feat, W1, y);

    cudaMemsetAsync(cnt, 0, N_NODES * sizeof(int), s1);
    hist_kernel<<<edge8_blocks, 256, 0, s1>>>(dst, cnt);
    scan_block_kernel<<<SCAN_NBLK, SCAN_B, 0, s1>>>(cnt, row_ptr, partials);
    scan_add_kernel<<<SCAN_NBLK, SCAN_B, 0, s1>>>(row_ptr, cursor, partials);
    fill_kernel<<<edge8_blocks, 256, 0, s1>>>(src, dst, cursor, col);
    cudaEventRecord(g_ctx.evCSR, s1);
    cudaStreamWaitEvent(s0, g_ctx.evCSR, 0);

    // ---- Layer 1 boundary: h = relu(y + Ay + b1) ----
    aggregate128_kernel<<<agg_blocks, 256, 0, s0>>>(y, row_ptr, col, b1, h);

    // ---- Layer 2: y = h @ W2 ; h = relu(y + Ay + b2) ----
    gemm_kernel<128><<<gemm_blocks, 128, smem128, s0>>>(h, W2, y);
    aggregate128_kernel<<<agg_blocks, 256, 0, s0>>>(y, row_ptr, col, b2, h);

    // ---- Layer 3: y = h @ W3 (64) ; out = relu(y + Ay + b3) ----
    gemm_kernel<64><<<gemm_blocks, 128, smem64, s0>>>(h, W3, y);
    aggregate64_kernel<<<agg_blocks, 256, 0, s0>>>(y, row_ptr, col, b3, out);
}